// round 5
// baseline (speedup 1.0000x reference)
#include <cuda_runtime.h>

#define HDIM 16
#define UDIM 7
#define HID  64
#define XDIM 23   // HDIM + UDIM

// tanh(x) = (e - 1)/(e + 1), e = exp(2x), via MUFU.EX2 + MUFU.RCP. ~1e-6 abs err.
__device__ __forceinline__ float fast_tanh(float x) {
    float xc = fminf(fmaxf(x, -15.0f), 15.0f);   // avoid inf*0 -> NaN
    float e;
    asm("ex2.approx.f32 %0, %1;" : "=f"(e) : "f"(xc * 2.8853900817779268f)); // 2*log2(e)
    float r;
    asm("rcp.approx.f32 %0, %1;" : "=f"(r) : "f"(e + 1.0f));
    return (e - 1.0f) * r;
}

__global__ __launch_bounds__(128, 1)
void node_scan_kernel(const float* __restrict__ U,
                      const float* __restrict__ W1, const float* __restrict__ b1,
                      const float* __restrict__ W2, const float* __restrict__ b2,
                      const float* __restrict__ W3, const float* __restrict__ b3,
                      const float* __restrict__ wd, const float* __restrict__ bd,
                      const float* __restrict__ wt, const float* __restrict__ bt,
                      const float* __restrict__ wc, const float* __restrict__ bc,
                      const float* __restrict__ h0,
                      float* __restrict__ out, int T)
{
    __shared__ __align__(16) float sx[24];    // x = [h(16), u(7)], sx[23]=0 pad
    __shared__ __align__(16) float sz1[64];
    __shared__ __align__(16) float sz2[64];

    const int tid = threadIdx.x;
    const float dt = (float)(5.0 / 60.0);

    // ---- role setup + weight loads into registers ----

    // Layer 1: warps 2-3 (tid 64..127), one full row each.
    float w1r[24];
    float b1r = 0.0f;
    if (tid >= 64) {
        const int r1 = tid - 64;
        #pragma unroll
        for (int j = 0; j < XDIM; ++j) w1r[j] = W1[r1 * XDIM + j];
        w1r[23] = 0.0f;
        b1r = b1[r1];
    }

    // Layer 2: all 128 threads; row = tid>>1, half = tid&1 (32 cols each).
    const int r2   = tid >> 1;
    const int half = tid & 1;
    float w2h[32];
    #pragma unroll
    for (int j = 0; j < 32; ++j) w2h[j] = W2[r2 * HID + half * 32 + j];
    const float b2r = b2[r2];

    // Layer 3: warps 0-1 (tid 0..63); row = tid>>2, seg = tid&3 (16 cols each).
    const int r3  = tid >> 2;
    const int seg = tid & 3;
    float w3s[16];
    float b3r = 0.0f;
    if (tid < 64) {
        #pragma unroll
        for (int j = 0; j < 16; ++j) w3s[j] = W3[r3 * HID + seg * 16 + j];
        b3r = b3[r3];
    }

    // Readouts: warp1 lanes 0-2 (tid 32..34).
    float rwr[16];
    float rb = 0.0f;
    if (tid >= 32 && tid < 35) {
        const int k = tid - 32;
        const float* rw = (k == 1) ? wt : (k == 2) ? wc : wd;
        rb = (k == 0) ? bd[0] : (k == 1) ? bt[0] : bc[0];
        #pragma unroll
        for (int j = 0; j < HDIM; ++j) rwr[j] = rw[j];
    }

    if (tid < 16) sx[tid] = h0[tid];
    if (tid == 0) sx[23] = 0.0f;

    // u handling: warp0 lanes 8-14 (tid 8..14), u index = tid-8.
    float ureg = 0.0f;
    if (tid >= 8 && tid < 8 + UDIM) ureg = U[tid - 8];

    const float4* sxv  = (const float4*)sx;
    const float4* sz1v = (const float4*)sz1;
    const float4* sz2v = (const float4*)sz2;

    for (int t = 0; t < T; ++t) {
        if (tid >= 8 && tid < 8 + UDIM) sx[HDIM + (tid - 8)] = ureg;
        __syncthreads();                                   // B1: [h_t, u_t] visible

        // prefetch u_{t+1} (hidden by step body)
        if (tid >= 8 && tid < 8 + UDIM && (t + 1) < T)
            ureg = U[(t + 1) * UDIM + (tid - 8)];

        if (tid >= 64) {
            // ---- layer 1: z1 = tanh(W1 x + b1), one row per thread ----
            float a0 = b1r, a1 = 0.f, a2 = 0.f, a3 = 0.f;
            #pragma unroll
            for (int q = 0; q < 6; ++q) {
                float4 v = sxv[q];
                a0 = fmaf(w1r[4 * q + 0], v.x, a0);
                a1 = fmaf(w1r[4 * q + 1], v.y, a1);
                a2 = fmaf(w1r[4 * q + 2], v.z, a2);
                a3 = fmaf(w1r[4 * q + 3], v.w, a3);
            }
            sz1[tid - 64] = fast_tanh((a0 + a1) + (a2 + a3));
        } else if (tid >= 32 && tid < 35) {
            // ---- readouts on h_t (reads complete before B2 < B3 < h update) ----
            float a0 = rb, a1 = 0.f, a2 = 0.f, a3 = 0.f;
            #pragma unroll
            for (int q = 0; q < 4; ++q) {
                float4 v = sxv[q];
                a0 = fmaf(rwr[4 * q + 0], v.x, a0);
                a1 = fmaf(rwr[4 * q + 1], v.y, a1);
                a2 = fmaf(rwr[4 * q + 2], v.z, a2);
                a3 = fmaf(rwr[4 * q + 3], v.w, a3);
            }
            out[(size_t)(tid - 32) * (size_t)T + (size_t)t] = (a0 + a1) + (a2 + a3);
        }
        __syncthreads();                                   // B2: z1 ready

        // ---- layer 2: z2 = tanh(W2 z1 + b2); row split across 2 threads ----
        {
            const int q0 = half * 8;                       // float4 offset: 0 or 8
            float a0 = 0.f, a1 = 0.f, a2 = 0.f, a3 = 0.f;
            #pragma unroll
            for (int q = 0; q < 8; ++q) {
                float4 v = sz1v[q0 + q];
                a0 = fmaf(w2h[4 * q + 0], v.x, a0);
                a1 = fmaf(w2h[4 * q + 1], v.y, a1);
                a2 = fmaf(w2h[4 * q + 2], v.z, a2);
                a3 = fmaf(w2h[4 * q + 3], v.w, a3);
            }
            float pr = (a0 + a1) + (a2 + a3);
            float tot = pr + __shfl_xor_sync(0xffffffffu, pr, 1);
            float z = fast_tanh(tot + b2r);
            if (half == 0) sz2[r2] = z;
        }
        __syncthreads();                                   // B3: z2 ready

        if (tid < 64) {
            // ---- layer 3: dh row r3 split across 4 threads; Euler update ----
            const int q0 = seg * 4;                        // float4 offset
            float a0 = 0.f, a1 = 0.f, a2 = 0.f, a3 = 0.f;
            #pragma unroll
            for (int q = 0; q < 4; ++q) {
                float4 v = sz2v[q0 + q];
                a0 = fmaf(w3s[4 * q + 0], v.x, a0);
                a1 = fmaf(w3s[4 * q + 1], v.y, a1);
                a2 = fmaf(w3s[4 * q + 2], v.z, a2);
                a3 = fmaf(w3s[4 * q + 3], v.w, a3);
            }
            float pr = (a0 + a1) + (a2 + a3);
            pr += __shfl_xor_sync(0xffffffffu, pr, 1);
            pr += __shfl_xor_sync(0xffffffffu, pr, 2);
            if (seg == 0)
                sx[r3] = fmaf(dt, pr + b3r, sx[r3]);       // h update
        }
        // next iteration's B1 publishes the new h
    }

    __syncthreads();
    if (tid < HDIM) out[(size_t)3 * (size_t)T + tid] = sx[tid];
}

extern "C" void kernel_launch(void* const* d_in, const int* in_sizes, int n_in,
                              void* d_out, int out_size)
{
    const float* U  = (const float*)d_in[0];
    const float* W1 = (const float*)d_in[1];
    const float* b1 = (const float*)d_in[2];
    const float* W2 = (const float*)d_in[3];
    const float* b2 = (const float*)d_in[4];
    const float* W3 = (const float*)d_in[5];
    const float* b3 = (const float*)d_in[6];
    const float* wd = (const float*)d_in[7];
    const float* bd = (const float*)d_in[8];
    const float* wt = (const float*)d_in[9];
    const float* bt = (const float*)d_in[10];
    const float* wc = (const float*)d_in[11];
    const float* bc = (const float*)d_in[12];
    const float* h0 = (const float*)d_in[13];
    float* out = (float*)d_out;

    const int T = in_sizes[0] / UDIM;

    node_scan_kernel<<<1, 128>>>(U, W1, b1, W2, b2, W3, b3,
                                 wd, bd, wt, bt, wc, bc, h0, out, T);
}

// round 6
// speedup vs baseline: 1.1977x; 1.1977x over previous
#include <cuda_runtime.h>
#include <cuda_bf16.h>

// Problem constants (shapes are fixed by the reference; T taken from in_sizes)
#define HDIM 16
#define UDIM 7
#define HID  64
#define XDIM 23   // HDIM + UDIM

// tanh(x) = (e - 1)/(e + 1), e = exp(2x), via MUFU.EX2 + MUFU.RCP. ~1e-6 abs err.
__device__ __forceinline__ float fast_tanh(float x) {
    float xc = fminf(fmaxf(x, -15.0f), 15.0f);   // avoid inf*0 -> NaN
    float e;
    asm("ex2.approx.f32 %0, %1;" : "=f"(e) : "f"(xc * 2.8853900817779268f)); // 2*log2(e)
    float r;
    asm("rcp.approx.f32 %0, %1;" : "=f"(r) : "f"(e + 1.0f));
    return (e - 1.0f) * r;
}

__global__ __launch_bounds__(64, 1)
void node_scan_kernel(const float* __restrict__ U,
                      const float* __restrict__ W1, const float* __restrict__ b1,
                      const float* __restrict__ W2, const float* __restrict__ b2,
                      const float* __restrict__ W3, const float* __restrict__ b3,
                      const float* __restrict__ wd, const float* __restrict__ bd,
                      const float* __restrict__ wt, const float* __restrict__ bt,
                      const float* __restrict__ wc, const float* __restrict__ bc,
                      const float* __restrict__ h0,
                      float* __restrict__ out, int T)
{
    __shared__ __align__(16) float sx[24];    // x = [h(16), u(7)], sx[23]=0 pad
    __shared__ __align__(16) float sz1[64];
    __shared__ __align__(16) float sz2[64];
    __shared__ float sp[16];                  // W3 partials (cols 32..63)
    __shared__ float srw[3][16];              // wd, wt, wc
    __shared__ float srb[3];                  // bd, bt, bc
    __shared__ float sb3[16];

    const int tid = threadIdx.x;
    const float dt = (float)(5.0 / 60.0);

    // ---- load per-thread weights into registers ----
    float w1r[24];
    #pragma unroll
    for (int j = 0; j < XDIM; ++j) w1r[j] = W1[tid * XDIM + j];
    w1r[23] = 0.0f;
    const float b1r = b1[tid];

    float w2r[64];
    #pragma unroll
    for (int j = 0; j < HID; ++j) w2r[j] = W2[tid * HID + j];
    const float b2r = b2[tid];

    // W3 split: warp0 lanes 0-15 -> rows, cols 0..31 ; lanes 16-31 -> rows, cols 32..63
    const int r3 = tid & 15;
    const int cb = (tid & 16) * 2;   // 0 or 32
    float w3r[32];
    #pragma unroll
    for (int j = 0; j < 32; ++j) w3r[j] = W3[r3 * HID + cb + j];

    if (tid < 16) {
        sx[tid]     = h0[tid];
        sb3[tid]    = b3[tid];
        srw[0][tid] = wd[tid];
        srw[1][tid] = wt[tid];
        srw[2][tid] = wc[tid];
    }
    if (tid == 0) {
        srb[0] = bd[0]; srb[1] = bt[0]; srb[2] = bc[0];
        sx[23] = 0.0f;
    }

    // prefetch u_0
    float ureg = (tid < UDIM) ? U[tid] : 0.0f;

    const float4* sxv  = (const float4*)sx;
    const float4* sz1v = (const float4*)sz1;
    const float4* sz2v = (const float4*)sz2;

    for (int t = 0; t < T; ++t) {
        if (tid < UDIM) sx[HDIM + tid] = ureg;
        __syncthreads();                         // B1: x = [h_t, u_t] visible

        // prefetch u_{t+1} (latency hidden by the step body)
        if (tid < UDIM && (t + 1) < T) ureg = U[(t + 1) * UDIM + tid];

        // ---- layer 1: z1 = tanh(W1 x + b1), one row per thread ----
        {
            float a0 = b1r, a1 = 0.f, a2 = 0.f, a3 = 0.f;
            #pragma unroll
            for (int q = 0; q < 6; ++q) {
                float4 v = sxv[q];
                a0 = fmaf(w1r[4*q+0], v.x, a0);
                a1 = fmaf(w1r[4*q+1], v.y, a1);
                a2 = fmaf(w1r[4*q+2], v.z, a2);
                a3 = fmaf(w1r[4*q+3], v.w, a3);
            }
            sz1[tid] = fast_tanh((a0 + a1) + (a2 + a3));
        }
        __syncthreads();                         // B2: z1 ready

        // ---- layer 2: z2 = tanh(W2 z1 + b2), one row per thread ----
        {
            float a0 = b2r, a1 = 0.f, a2 = 0.f, a3 = 0.f;
            #pragma unroll
            for (int q = 0; q < 16; ++q) {
                float4 v = sz1v[q];
                a0 = fmaf(w2r[4*q+0], v.x, a0);
                a1 = fmaf(w2r[4*q+1], v.y, a1);
                a2 = fmaf(w2r[4*q+2], v.z, a2);
                a3 = fmaf(w2r[4*q+3], v.w, a3);
            }
            sz2[tid] = fast_tanh((a0 + a1) + (a2 + a3));
        }
        __syncthreads();                         // B3: z2 ready

        // ---- layer 3 (warp0, no intra-warp divergence) + readouts (warp1) ----
        float pr = 0.0f;
        if (tid < 32) {
            const int q0 = (tid & 16) >> 1;      // float4 offset: 0 or 8
            float c0 = 0.f, c1 = 0.f, c2 = 0.f, c3 = 0.f;
            #pragma unroll
            for (int q = 0; q < 8; ++q) {
                float4 v = sz2v[q0 + q];
                c0 = fmaf(w3r[4*q+0], v.x, c0);
                c1 = fmaf(w3r[4*q+1], v.y, c1);
                c2 = fmaf(w3r[4*q+2], v.z, c2);
                c3 = fmaf(w3r[4*q+3], v.w, c3);
            }
            pr = (c0 + c1) + (c2 + c3);
            if (tid >= 16) sp[tid & 15] = pr;    // cols 32..63 partial
        } else if (tid < 35) {
            // readouts use h_t (sx is not updated until after B4)
            const int k = tid - 32;
            float acc = srb[k];
            #pragma unroll
            for (int j = 0; j < HDIM; ++j)
                acc = fmaf(srw[k][j], sx[j], acc);
            out[(size_t)k * (size_t)T + (size_t)t] = acc;
        }
        __syncthreads();                         // B4: partials + readout reads done

        // ---- Euler update: h += dt * (W3 z2 + b3) ----
        if (tid < 16) {
            float dh = pr + sp[tid] + sb3[tid];
            sx[tid] = fmaf(dt, dh, sx[tid]);
        }
        // next iteration's B1 makes the new h visible to all threads
    }

    __syncthreads();
    if (tid < HDIM) out[(size_t)3 * (size_t)T + tid] = sx[tid];
}

extern "C" void kernel_launch(void* const* d_in, const int* in_sizes, int n_in,
                              void* d_out, int out_size)
{
    const float* U  = (const float*)d_in[0];
    const float* W1 = (const float*)d_in[1];
    const float* b1 = (const float*)d_in[2];
    const float* W2 = (const float*)d_in[3];
    const float* b2 = (const float*)d_in[4];
    const float* W3 = (const float*)d_in[5];
    const float* b3 = (const float*)d_in[6];
    const float* wd = (const float*)d_in[7];
    const float* bd = (const float*)d_in[8];
    const float* wt = (const float*)d_in[9];
    const float* bt = (const float*)d_in[10];
    const float* wc = (const float*)d_in[11];
    const float* bc = (const float*)d_in[12];
    const float* h0 = (const float*)d_in[13];
    float* out = (float*)d_out;

    const int T = in_sizes[0] / UDIM;

    node_scan_kernel<<<1, 64>>>(U, W1, b1, W2, b2, W3, b3,
                                wd, bd, wt, bt, wc, bc, h0, out, T);
}

// round 7
// speedup vs baseline: 1.3482x; 1.1257x over previous
#include <cuda_runtime.h>

#define HDIM 16
#define UDIM 7
#define HID  64
#define XDIM 23   // HDIM + UDIM

__global__ __launch_bounds__(64, 1)
void node_scan_kernel(const float* __restrict__ U,
                      const float* __restrict__ W1, const float* __restrict__ b1,
                      const float* __restrict__ W2, const float* __restrict__ b2,
                      const float* __restrict__ W3, const float* __restrict__ b3,
                      const float* __restrict__ wd, const float* __restrict__ bd,
                      const float* __restrict__ wt, const float* __restrict__ bt,
                      const float* __restrict__ wc, const float* __restrict__ bc,
                      const float* __restrict__ h0,
                      float* __restrict__ out, int T)
{
    __shared__ __align__(16) float sx[24];    // x = [h(16), u(7)], sx[23]=0 pad
    __shared__ __align__(16) float sz1[64];
    __shared__ __align__(16) float sz2[64];

    const int tid = threadIdx.x;
    const float dt = (float)(5.0 / 60.0);

    // ---- per-thread weights in registers ----
    float w1r[24];
    #pragma unroll
    for (int j = 0; j < XDIM; ++j) w1r[j] = W1[tid * XDIM + j];
    w1r[23] = 0.0f;
    const float b1r = b1[tid];

    float w2r[64];
    #pragma unroll
    for (int j = 0; j < HID; ++j) w2r[j] = W2[tid * HID + j];
    const float b2r = b2[tid];

    // warp0: W3 split — lane = (row r3, col-half cb); halves joined by shfl_xor(16)
    const int r3 = tid & 15;
    const int cb = (tid & 16) * 2;                 // 0 or 32
    float w3r[32];
    float b3r = 0.0f;
    if (tid < 32) {
        #pragma unroll
        for (int j = 0; j < 32; ++j) w3r[j] = W3[r3 * HID + cb + j];
        b3r = b3[r3];
    }

    // warp1 lanes 0..2: readout weights (wd/wt/wc) in registers
    float rwr[16];
    float rb = 0.0f;
    if (tid >= 32 && tid < 35) {
        const int k = tid - 32;
        const float* rw = (k == 1) ? wt : (k == 2) ? wc : wd;
        rb = (k == 0) ? bd[0] : (k == 1) ? bt[0] : bc[0];
        #pragma unroll
        for (int j = 0; j < HDIM; ++j) rwr[j] = rw[j];
    }

    if (tid < 16) sx[tid] = h0[tid];
    if (tid == 0) sx[23] = 0.0f;

    float ureg = (tid < UDIM) ? U[tid] : 0.0f;     // prefetch u_0

    const float4* sxv  = (const float4*)sx;
    const float4* sz1v = (const float4*)sz1;
    const float4* sz2v = (const float4*)sz2;

    float* outp = out + (size_t)(tid & 31) * (size_t)T;  // row base, warp1 lanes 0..2

    for (int t = 0; t < T; ++t) {
        if (tid < UDIM) sx[HDIM + tid] = ureg;
        __syncthreads();                           // B1: [h_t, u_t] visible

        // prefetch u_{t+1} (latency hidden by step body)
        if (tid < UDIM && (t + 1) < T) ureg = U[(t + 1) * UDIM + tid];

        // warp1: snapshot h_t (readouts run later, race-free vs the h-update)
        float hsn[16];
        if (tid >= 32) {
            #pragma unroll
            for (int q = 0; q < 4; ++q) {
                float4 v = sxv[q];
                hsn[4 * q + 0] = v.x; hsn[4 * q + 1] = v.y;
                hsn[4 * q + 2] = v.z; hsn[4 * q + 3] = v.w;
            }
        }

        // ---- layer 1: z1 = tanh(W1 x + b1), one row per thread ----
        {
            float a0 = b1r, a1 = 0.f, a2 = 0.f, a3 = 0.f;
            #pragma unroll
            for (int q = 0; q < 6; ++q) {
                float4 v = sxv[q];
                a0 = fmaf(w1r[4 * q + 0], v.x, a0);
                a1 = fmaf(w1r[4 * q + 1], v.y, a1);
                a2 = fmaf(w1r[4 * q + 2], v.z, a2);
                a3 = fmaf(w1r[4 * q + 3], v.w, a3);
            }
            sz1[tid] = tanhf((a0 + a1) + (a2 + a3));
        }
        __syncthreads();                           // B2: z1 ready

        // ---- layer 2: z2 = tanh(W2 z1 + b2), one row per thread ----
        {
            float a0 = b2r, a1 = 0.f, a2 = 0.f, a3 = 0.f;
            #pragma unroll
            for (int q = 0; q < 16; ++q) {
                float4 v = sz1v[q];
                a0 = fmaf(w2r[4 * q + 0], v.x, a0);
                a1 = fmaf(w2r[4 * q + 1], v.y, a1);
                a2 = fmaf(w2r[4 * q + 2], v.z, a2);
                a3 = fmaf(w2r[4 * q + 3], v.w, a3);
            }
            sz2[tid] = tanhf((a0 + a1) + (a2 + a3));
        }
        __syncthreads();                           // B3: z2 ready

        if (tid < 32) {
            // ---- layer 3: dh row r3, 32 cols per lane; halves joined by shfl ----
            const int q0 = cb >> 2;                // float4 offset: 0 or 8
            float c0 = 0.f, c1 = 0.f, c2 = 0.f, c3 = 0.f;
            #pragma unroll
            for (int q = 0; q < 8; ++q) {
                float4 v = sz2v[q0 + q];
                c0 = fmaf(w3r[4 * q + 0], v.x, c0);
                c1 = fmaf(w3r[4 * q + 1], v.y, c1);
                c2 = fmaf(w3r[4 * q + 2], v.z, c2);
                c3 = fmaf(w3r[4 * q + 3], v.w, c3);
            }
            float pr = (c0 + c1) + (c2 + c3);
            float prx = __shfl_xor_sync(0xffffffffu, pr, 16);
            if (tid < 16) {
                float dh = pr + prx + b3r;
                sx[tid] = fmaf(dt, dh, sx[tid]);   // Euler update
            }
        } else if (tid < 35) {
            // ---- readouts on h_t snapshot ----
            float a0 = rb, a1 = 0.f, a2 = 0.f, a3 = 0.f;
            #pragma unroll
            for (int j = 0; j < 4; ++j) {
                a0 = fmaf(rwr[4 * j + 0], hsn[4 * j + 0], a0);
                a1 = fmaf(rwr[4 * j + 1], hsn[4 * j + 1], a1);
                a2 = fmaf(rwr[4 * j + 2], hsn[4 * j + 2], a2);
                a3 = fmaf(rwr[4 * j + 3], hsn[4 * j + 3], a3);
            }
            outp[t] = (a0 + a1) + (a2 + a3);
        }
        // next iteration's B1 publishes the new h
    }

    __syncthreads();
    if (tid < HDIM) out[(size_t)3 * (size_t)T + tid] = sx[tid];
}

extern "C" void kernel_launch(void* const* d_in, const int* in_sizes, int n_in,
                              void* d_out, int out_size)
{
    const float* U  = (const float*)d_in[0];
    const float* W1 = (const float*)d_in[1];
    const float* b1 = (const float*)d_in[2];
    const float* W2 = (const float*)d_in[3];
    const float* b2 = (const float*)d_in[4];
    const float* W3 = (const float*)d_in[5];
    const float* b3 = (const float*)d_in[6];
    const float* wd = (const float*)d_in[7];
    const float* bd = (const float*)d_in[8];
    const float* wt = (const float*)d_in[9];
    const float* bt = (const float*)d_in[10];
    const float* wc = (const float*)d_in[11];
    const float* bc = (const float*)d_in[12];
    const float* h0 = (const float*)d_in[13];
    float* out = (float*)d_out;

    const int T = in_sizes[0] / UDIM;

    node_scan_kernel<<<1, 64>>>(U, W1, b1, W2, b2, W3, b3,
                                wd, bd, wt, bt, wc, bc, h0, out, T);
}